// round 4
// baseline (speedup 1.0000x reference)
#include <cuda_runtime.h>
#include <math.h>

// ---------------- problem constants ----------------
#define NPIX     32768        // 32 * 32 * 32 pixels
#define NE       1024         // codebook entries
#define KDIM     256          // embedding dim
#define BETA     0.25f
#define EPS_P    1e-10f

// output layout (concatenated, float32):
// [0]                loss
// [1 .. 8388608]     z_q      (B,C,H,W) = same linear layout as input z
// [8388609]          perplexity
// [8388610 ..]       idx (32768, cast to float)
// [8421378 ..]       z_q1     (same layout as z)
#define ZQ_OFF    1ull
#define PERP_OFF  8388609ull
#define IDX_OFF   8388610ull
#define ZQ1_OFF   8421378ull

// ---------------- argmin GEMM tiling ----------------
#define MT   128              // pixels per CTA
#define CT   128              // codes per tile
#define KT   32               // k per B-tile
// Bs layout: float2 pairs, pair-major: pair p holds codes (2p, 2p+1) for k=0..31,
// padded stride 33 float2 (66 floats) per pair -> conflict-free 64-bit reads.
#define BS_PAIR_STRIDE 33     // in float2 units (32 k-values + 1 pad)
#define SMEM_A_FLOATS  (KDIM * MT)                 // 32768
#define SMEM_B_FLOATS  (64 * BS_PAIR_STRIDE * 2)   // 4224
#define SMEM_H_FLOATS  (NE)                        // 1024
#define SMEM_ARGMIN_BYTES ((SMEM_A_FLOATS + SMEM_B_FLOATS + SMEM_H_FLOATS) * 4)

// ---------------- device scratch ----------------
__device__ int   g_idx[NPIX];
__device__ float g_hn[NE];
__device__ float g_partials[1024];
__device__ int   g_hist[NE];

// ---------------- f32x2 helpers ----------------
__device__ __forceinline__ unsigned long long pack2(float lo, float hi) {
    unsigned long long r;
    asm("mov.b64 %0, {%1, %2};" : "=l"(r) : "f"(lo), "f"(hi));
    return r;
}
__device__ __forceinline__ void unpack2(unsigned long long v, float& lo, float& hi) {
    asm("mov.b64 {%0, %1}, %2;" : "=f"(lo), "=f"(hi) : "l"(v));
}
__device__ __forceinline__ void fma2(unsigned long long& d, unsigned long long a, unsigned long long b) {
    asm("fma.rn.f32x2 %0, %1, %2, %0;" : "+l"(d) : "l"(a), "l"(b));
}

// ---------------- kernel 0: half squared norms of codebook ----------------
__global__ void halfnorm_kernel(const float* __restrict__ emb) {
    int c = blockIdx.x * 256 + threadIdx.x;   // 0..1023
    const float* e = emb + c * KDIM;
    float s = 0.0f;
    #pragma unroll
    for (int i = 0; i < KDIM; i += 4) {
        float4 v = *(const float4*)(e + i);
        s += v.x * v.x + v.y * v.y + v.z * v.z + v.w * v.w;
    }
    g_hn[c] = 0.5f * s;
}

// ---------------- kernel A: argmax(z.e - 0.5||e||^2) over 1024 codes ----------------
// grid 256 blocks x 256 threads. thread (tx=t&15, ty=t>>4) computes
// pixels {8*ty + i, i<8} x codes {32*j + 2*tx + s, j<4, s<2} per code tile.
__global__ void __launch_bounds__(256, 1)
argmin_kernel(const float* __restrict__ z, const float* __restrict__ emb) {
    extern __shared__ float sm[];
    float* As = sm;                                   // [k][m] : KDIM x MT
    float* Bsf = sm + SMEM_A_FLOATS;                  // pair-major float2 tiles
    float* hn = sm + SMEM_A_FLOATS + SMEM_B_FLOATS;   // [1024]
    unsigned long long* Bs64 = (unsigned long long*)Bsf;

    const int t  = threadIdx.x;
    const int tx = t & 15;
    const int ty = t >> 4;
    const int m0 = blockIdx.x * MT;
    const float* zb = z + (size_t)(m0 >> 10) * (KDIM * 1024) + (m0 & 1023);

    // load A tile: As[k*128 + m], full K, coalesced float4
    #pragma unroll
    for (int r = 0; r < 32; r++) {
        int q = t + 256 * r;                // 0..8191 float4s
        int k = q >> 5;
        int m4 = (q & 31) << 2;
        float4 v = *(const float4*)(zb + (size_t)k * 1024 + m4);
        *(float4*)(As + k * MT + m4) = v;
    }
    // load half-norms
    #pragma unroll
    for (int r = 0; r < 4; r++) hn[t + 256 * r] = g_hn[t + 256 * r];

    float best[8];
    int   bidx[8];
    #pragma unroll
    for (int i = 0; i < 8; i++) { best[i] = -INFINITY; bidx[i] = 0; }

    for (int ct = 0; ct < NE / CT; ct++) {
        unsigned long long acc[8][4];
        #pragma unroll
        for (int i = 0; i < 8; i++)
            #pragma unroll
            for (int j = 0; j < 4; j++) acc[i][j] = 0ull;

        for (int kt = 0; kt < KDIM / KT; kt++) {
            __syncthreads();
            // load B tile: 128 codes x 32 k, store as float2 pairs [pair][k]
            #pragma unroll
            for (int r = 0; r < 4; r++) {
                int q = t + 256 * r;            // 0..1023 float4s
                int code = q >> 3;              // 0..127
                int kv = (q & 7) << 2;          // 0..28
                float4 v = *(const float4*)(emb + (size_t)(ct * CT + code) * KDIM + kt * KT + kv);
                int base = (code >> 1) * (BS_PAIR_STRIDE * 2) + (code & 1);
                Bsf[base + (kv + 0) * 2] = v.x;
                Bsf[base + (kv + 1) * 2] = v.y;
                Bsf[base + (kv + 2) * 2] = v.z;
                Bsf[base + (kv + 3) * 2] = v.w;
            }
            __syncthreads();

            #pragma unroll 8
            for (int kk = 0; kk < KT; kk++) {
                int k = kt * KT + kk;
                float4 a0 = *(const float4*)(As + k * MT + ty * 8);
                float4 a1 = *(const float4*)(As + k * MT + ty * 8 + 4);
                unsigned long long a2[8];
                a2[0] = pack2(a0.x, a0.x); a2[1] = pack2(a0.y, a0.y);
                a2[2] = pack2(a0.z, a0.z); a2[3] = pack2(a0.w, a0.w);
                a2[4] = pack2(a1.x, a1.x); a2[5] = pack2(a1.y, a1.y);
                a2[6] = pack2(a1.z, a1.z); a2[7] = pack2(a1.w, a1.w);
                unsigned long long b2[4];
                #pragma unroll
                for (int j = 0; j < 4; j++)
                    b2[j] = Bs64[(j * 16 + tx) * BS_PAIR_STRIDE + kk];
                #pragma unroll
                for (int i = 0; i < 8; i++)
                    #pragma unroll
                    for (int j = 0; j < 4; j++)
                        fma2(acc[i][j], a2[i], b2[j]);
            }
        }

        // epilogue for this code tile
        #pragma unroll
        for (int i = 0; i < 8; i++) {
            #pragma unroll
            for (int j = 0; j < 4; j++) {
                float lo, hi;
                unpack2(acc[i][j], lo, hi);
                int c0 = ct * CT + j * 32 + 2 * tx;
                float vlo = lo - hn[c0];
                float vhi = hi - hn[c0 + 1];
                if (vlo > best[i]) { best[i] = vlo; bidx[i] = c0; }
                if (vhi > best[i]) { best[i] = vhi; bidx[i] = c0 + 1; }
            }
        }
    }

    // reduce across the 16 tx lanes sharing each pixel row (tie -> lower idx)
    #pragma unroll
    for (int i = 0; i < 8; i++) {
        float v = best[i];
        int id = bidx[i];
        #pragma unroll
        for (int m = 8; m >= 1; m >>= 1) {
            float ov = __shfl_xor_sync(0xffffffffu, v, m);
            int   oi = __shfl_xor_sync(0xffffffffu, id, m);
            if (ov > v || (ov == v && oi < id)) { v = ov; id = oi; }
        }
        if (tx == 0) g_idx[m0 + ty * 8 + i] = id;
    }
}

// ---------------- kernel B1: gather z_q/z_q1 + squared-error partials ----------------
// block handles 32 consecutive pixels (within one b), 256 threads
__global__ void __launch_bounds__(256)
gather_kernel(const float* __restrict__ z, const float* __restrict__ emb,
              float* __restrict__ out) {
    __shared__ float se[32][257];
    __shared__ int sidx[32];
    __shared__ float red[256];
    const int t = threadIdx.x;
    const int n0 = blockIdx.x * 32;
    if (t < 32) sidx[t] = g_idx[n0 + t];
    __syncthreads();
    // load 32 codebook rows into smem (coalesced)
    #pragma unroll
    for (int r = 0; r < 8; r++) {
        int q = t + 256 * r;            // 0..2047 float4s
        int row = q >> 6;
        int c4 = (q & 63) << 2;
        float4 v = *(const float4*)(emb + (size_t)sidx[row] * KDIM + c4);
        se[row][c4 + 0] = v.x; se[row][c4 + 1] = v.y;
        se[row][c4 + 2] = v.z; se[row][c4 + 3] = v.w;
    }
    __syncthreads();
    const int hw = t & 31;
    const int cg = t >> 5;
    const int b = n0 >> 10;
    const int hwg = (n0 & 1023) + hw;
    const size_t zbase = (size_t)b * (KDIM * 1024) + hwg;
    float acc = 0.0f;
    #pragma unroll
    for (int ci = 0; ci < 32; ci++) {
        int c = cg * 32 + ci;
        float v = se[hw][c];
        size_t off = zbase + (size_t)c * 1024;
        float zv = z[off];
        float d = v - zv;
        acc += d * d;
        out[ZQ_OFF + off] = v;
        out[ZQ1_OFF + off] = v;
    }
    red[t] = acc;
    __syncthreads();
    #pragma unroll
    for (int s = 128; s > 0; s >>= 1) {
        if (t < s) red[t] += red[t + s];
        __syncthreads();
    }
    if (t == 0) g_partials[blockIdx.x] = red[0];
}

// ---------------- kernel B2: histogram + idx-as-float output ----------------
__global__ void hist_kernel(float* __restrict__ out) {
    __shared__ int h[NE];
    const int t = threadIdx.x;   // 1024 threads, 1 block
    h[t] = 0;
    __syncthreads();
    for (int n = t; n < NPIX; n += 1024) {
        int id = g_idx[n];
        atomicAdd(&h[id], 1);
        out[IDX_OFF + n] = (float)id;
    }
    __syncthreads();
    g_hist[t] = h[t];
}

// ---------------- kernel B3: loss + perplexity ----------------
__global__ void finalize_kernel(float* __restrict__ out) {
    __shared__ float red[1024];
    const int t = threadIdx.x;   // 1024 threads, 1 block
    red[t] = g_partials[t];
    __syncthreads();
    #pragma unroll
    for (int s = 512; s > 0; s >>= 1) {
        if (t < s) red[t] += red[t + s];
        __syncthreads();
    }
    float loss = red[0] * (1.0f + BETA) / 8388608.0f;
    __syncthreads();
    float p = (float)g_hist[t] / (float)NPIX;
    red[t] = p * logf(p + EPS_P);
    __syncthreads();
    #pragma unroll
    for (int s = 512; s > 0; s >>= 1) {
        if (t < s) red[t] += red[t + s];
        __syncthreads();
    }
    if (t == 0) {
        out[0] = loss;
        out[PERP_OFF] = expf(-red[0]);
    }
}

// ---------------- launch ----------------
extern "C" void kernel_launch(void* const* d_in, const int* in_sizes, int n_in,
                              void* d_out, int out_size) {
    const float* z   = (const float*)d_in[0];
    const float* emb = (const float*)d_in[1];
    float* out = (float*)d_out;

    halfnorm_kernel<<<4, 256>>>(emb);

    cudaFuncSetAttribute(argmin_kernel,
                         cudaFuncAttributeMaxDynamicSharedMemorySize,
                         SMEM_ARGMIN_BYTES);
    argmin_kernel<<<NPIX / MT, 256, SMEM_ARGMIN_BYTES>>>(z, emb);

    gather_kernel<<<NPIX / 32, 256>>>(z, emb, out);
    hist_kernel<<<1, 1024>>>(out);
    finalize_kernel<<<1, 1024>>>(out);
}

// round 6
// speedup vs baseline: 1.1967x; 1.1967x over previous
#include <cuda_runtime.h>
#include <math.h>
#include <stdint.h>

// ---------------- problem constants ----------------
#define NPIX     32768
#define NE       1024
#define KDIM     256
#define BETA     0.25f
#define EPS_P    1e-10f

// output layout (concatenated, float32)
#define ZQ_OFF    1ull
#define PERP_OFF  8388609ull
#define IDX_OFF   8388610ull
#define ZQ1_OFF   8421378ull

// ---------------- device scratch ----------------
__device__ int   g_idx[NPIX];
__device__ float g_hn_g[NE];
__device__ int   g_hist[NE];
__device__ float g_partials[1024];
// emb split to tf32 hi/lo, with k pair-permuted within each 8-block:
// j = k&7: j<4 -> 2j, j>=4 -> 2(j-4)+1  => (k, k+4) adjacent pairs
__device__ float g_ehi[NE * KDIM];
__device__ float g_elo[NE * KDIM];

// ---------------- smem layout (floats) ----------------
// As   [0, 33280)        : A fp32 [128 rows][260]  (cols = permuted k)
// Bs   [33280, 51712)    : 4 bufs (2 stages x hi/lo) of 4608 = [128 n][36]
// hn   [51712, 52736)    : 1024
// redv [52736, 52992)    : 256
// redi [52992, 53248)    : 256 (int)
#define AS_STRIDE 260
#define SMF_BS    33280
#define SMF_HN    51712
#define SMF_REDV  52736
#define SMF_REDI  52992
#define SMF_TOTAL 53248
#define BUF_FLOATS 4608

static __device__ __forceinline__ uint32_t smem_u32(const void* p) {
    uint32_t a;
    asm("{ .reg .u64 t; cvta.to.shared.u64 t, %1; cvt.u32.u64 %0, t; }" : "=r"(a) : "l"(p));
    return a;
}
static __device__ __forceinline__ uint32_t f2tf32(float f) {
    uint32_t u; asm("cvt.rna.tf32.f32 %0, %1;" : "=r"(u) : "f"(f)); return u;
}
static __device__ __forceinline__ void cp16(uint32_t smem, const void* g) {
    asm volatile("cp.async.cg.shared.global [%0], [%1], 16;" :: "r"(smem), "l"(g) : "memory");
}
#define CP_COMMIT() asm volatile("cp.async.commit_group;" ::: "memory")
#define CP_WAIT1()  asm volatile("cp.async.wait_group 1;" ::: "memory")
#define CP_WAIT0()  asm volatile("cp.async.wait_group 0;" ::: "memory")

static __device__ __forceinline__ void mma8(float* c, const uint32_t* a, const uint32_t* b) {
    asm volatile(
        "mma.sync.aligned.m16n8k8.row.col.f32.tf32.tf32.f32 "
        "{%0,%1,%2,%3}, {%4,%5,%6,%7}, {%8,%9}, {%0,%1,%2,%3};"
        : "+f"(c[0]), "+f"(c[1]), "+f"(c[2]), "+f"(c[3])
        : "r"(a[0]), "r"(a[1]), "r"(a[2]), "r"(a[3]), "r"(b[0]), "r"(b[1]));
}

// k permutation within 8-blocks: (k, k+4) become adjacent
static __device__ __forceinline__ int kperm(int k) {
    return (k & ~7) | (((k & 3) << 1) | ((k >> 2) & 1));
}

// ---------------- kernel 0: split emb -> tf32 hi/lo (permuted) + half norms + zero hist ----------------
__global__ void split_kernel(const float* __restrict__ emb) {
    __shared__ float red[256];
    const int c = blockIdx.x;        // 1024 blocks
    const int t = threadIdx.x;       // 256 threads = one k each
    float f = emb[c * KDIM + t];
    uint32_t hu = f2tf32(f);
    float hf = __uint_as_float(hu);
    uint32_t lu = f2tf32(f - hf);
    int kp = kperm(t);
    g_ehi[c * KDIM + kp] = __uint_as_float(hu);
    g_elo[c * KDIM + kp] = __uint_as_float(lu);
    red[t] = f * f;
    __syncthreads();
    #pragma unroll
    for (int s = 128; s > 0; s >>= 1) {
        if (t < s) red[t] += red[t + s];
        __syncthreads();
    }
    if (t == 0) { g_hn_g[c] = 0.5f * red[0]; g_hist[c] = 0; }
}

// ---------------- kernel A: mma.sync 3xTF32 argmax ----------------
// 256 threads, 8 warps = 4 M-groups x 2 N-groups; warp tile 32(M) x 64(N).
// Per CTA: 128 pixels x 1024 codes, K=256.
__global__ void __launch_bounds__(256, 1)
argmin_mma_kernel(const float* __restrict__ z) {
    extern __shared__ float sm[];
    float* As   = sm;
    float* hn   = sm + SMF_HN;
    float* redv = sm + SMF_REDV;
    int*   redi = (int*)(sm + SMF_REDI);
    const uint32_t sb = smem_u32(sm);

    const int tid = threadIdx.x;
    const int wid = tid >> 5;
    const int l   = tid & 31;
    const int qr  = l >> 2;
    const int qc  = l & 3;
    const int mb  = (wid >> 1) * 32;
    const int nb  = (wid & 1) * 64;
    const int m0  = blockIdx.x * 128;

    // ---- prologue: load A (z tile) into smem, column-permuted; load hn ----
    {
        const int k = tid;
        const int kp = kperm(k);
        const float* zr = z + (size_t)(((m0 >> 10) * 256 + k)) * 1024 + (m0 & 1023);
        #pragma unroll
        for (int r = 0; r < 32; r++) {
            float4 v = *(const float4*)(zr + r * 4);
            As[(r * 4 + 0) * AS_STRIDE + kp] = v.x;
            As[(r * 4 + 1) * AS_STRIDE + kp] = v.y;
            As[(r * 4 + 2) * AS_STRIDE + kp] = v.z;
            As[(r * 4 + 3) * AS_STRIDE + kp] = v.w;
        }
        #pragma unroll
        for (int r = 0; r < 4; r++) hn[tid + 256 * r] = g_hn_g[tid + 256 * r];
    }

    // ---- B chunk loader: chunk it = (ct*8 + kc): 128 codes x 32 k (hi+lo) ----
    auto load_chunk = [&](int it, int stage) {
        const int ct = it >> 3, kc = it & 7;
        const float* ghi = g_ehi + (size_t)(ct * 128) * KDIM + kc * 32;
        const float* glo = g_elo + (size_t)(ct * 128) * KDIM + kc * 32;
        const uint32_t dhi = sb + (SMF_BS + (stage * 2 + 0) * BUF_FLOATS) * 4;
        const uint32_t dlo = sb + (SMF_BS + (stage * 2 + 1) * BUF_FLOATS) * 4;
        #pragma unroll
        for (int r = 0; r < 4; r++) {
            int q = tid + 256 * r;          // 0..1023
            int n = q >> 3, j = q & 7;      // code, 16B unit
            cp16(dhi + (n * 36 + j * 4) * 4, ghi + (size_t)n * KDIM + j * 4);
            cp16(dlo + (n * 36 + j * 4) * 4, glo + (size_t)n * KDIM + j * 4);
        }
        CP_COMMIT();
    };

    load_chunk(0, 0);
    __syncthreads();   // As + hn visible

    float best[4];
    int   bidx[4];
    #pragma unroll
    for (int s = 0; s < 4; s++) { best[s] = -INFINITY; bidx[s] = 0; }

    for (int ct = 0; ct < 8; ct++) {
        float acc[2][8][4];
        #pragma unroll
        for (int mf = 0; mf < 2; mf++)
            #pragma unroll
            for (int nf = 0; nf < 8; nf++)
                #pragma unroll
                for (int cc = 0; cc < 4; cc++) acc[mf][nf][cc] = 0.0f;

        for (int kc = 0; kc < 8; kc++) {
            const int it = ct * 8 + kc;
            const int stage = it & 1;
            if (it + 1 < 64) { load_chunk(it + 1, stage ^ 1); CP_WAIT1(); }
            else             { CP_WAIT0(); }
            __syncthreads();

            const float* bhB = sm + SMF_BS + (stage * 2 + 0) * BUF_FLOATS;
            const float* blB = sm + SMF_BS + (stage * 2 + 1) * BUF_FLOATS;

            #pragma unroll
            for (int ks = 0; ks < 4; ks++) {
                // A fragments: (k, k+4) adjacent due to permuted columns
                uint32_t ahi[2][4], alo[2][4];
                #pragma unroll
                for (int mf = 0; mf < 2; mf++)
                    #pragma unroll
                    for (int h = 0; h < 2; h++) {
                        int row = mb + qr + mf * 16 + h * 8;
                        float2 f = *(const float2*)(As + row * AS_STRIDE + kc * 32 + ks * 8 + 2 * qc);
                        uint32_t hx = f2tf32(f.x);
                        uint32_t hy = f2tf32(f.y);
                        ahi[mf][h]     = hx;
                        ahi[mf][h + 2] = hy;
                        alo[mf][h]     = f2tf32(f.x - __uint_as_float(hx));
                        alo[mf][h + 2] = f2tf32(f.y - __uint_as_float(hy));
                    }
                #pragma unroll
                for (int nf = 0; nf < 8; nf++) {
                    const int n = nb + nf * 8 + qr;
                    float2 bh = *(const float2*)(bhB + n * 36 + ks * 8 + 2 * qc);
                    float2 bl = *(const float2*)(blB + n * 36 + ks * 8 + 2 * qc);
                    uint32_t bhr[2] = { __float_as_uint(bh.x), __float_as_uint(bh.y) };
                    uint32_t blr[2] = { __float_as_uint(bl.x), __float_as_uint(bl.y) };
                    #pragma unroll
                    for (int mf = 0; mf < 2; mf++) {
                        mma8(acc[mf][nf], ahi[mf], bhr);
                        mma8(acc[mf][nf], ahi[mf], blr);
                        mma8(acc[mf][nf], alo[mf], bhr);
                    }
                }
            }
            __syncthreads();   // protect stage reuse
        }

        // epilogue: subtract half-norm, fold into running argmax
        #pragma unroll
        for (int mf = 0; mf < 2; mf++)
            #pragma unroll
            for (int nf = 0; nf < 8; nf++)
                #pragma unroll
                for (int cc = 0; cc < 4; cc++) {
                    int col = nb + nf * 8 + 2 * qc + (cc & 1);
                    int code = ct * 128 + col;
                    float s = acc[mf][nf][cc] - hn[code];
                    int slot = mf * 2 + (cc >> 1);
                    if (s > best[slot]) { best[slot] = s; bidx[slot] = code; }
                }
    }

    // reduce across the 4 lanes of each quad (rows shared by qc)
    #pragma unroll
    for (int s = 0; s < 4; s++) {
        float v = best[s];
        int id = bidx[s];
        #pragma unroll
        for (int m = 1; m <= 2; m <<= 1) {
            float ov = __shfl_xor_sync(0xffffffffu, v, m);
            int   oi = __shfl_xor_sync(0xffffffffu, id, m);
            if (ov > v || (ov == v && oi < id)) { v = ov; id = oi; }
        }
        if (qc == 0) {
            int row = mb + qr + (s >> 1) * 16 + (s & 1) * 8;
            redv[row * 2 + (wid & 1)] = v;
            redi[row * 2 + (wid & 1)] = id;
        }
    }
    __syncthreads();
    if (tid < 128) {
        float v0 = redv[tid * 2], v1 = redv[tid * 2 + 1];
        int   i0 = redi[tid * 2], i1 = redi[tid * 2 + 1];
        int id = (v1 > v0 || (v1 == v0 && i1 < i0)) ? i1 : i0;
        g_idx[m0 + tid] = id;
    }
}

// ---------------- kernel B1: gather z_q/z_q1 + squared-error partials + idx out ----------------
__global__ void __launch_bounds__(256)
gather_kernel(const float* __restrict__ z, const float* __restrict__ emb,
              float* __restrict__ out) {
    __shared__ float se[32][257];
    __shared__ int sidx[32];
    __shared__ float red[256];
    const int t = threadIdx.x;
    const int n0 = blockIdx.x * 32;
    if (t < 32) sidx[t] = g_idx[n0 + t];
    __syncthreads();
    if (t < 32) out[IDX_OFF + n0 + t] = (float)sidx[t];
    #pragma unroll
    for (int r = 0; r < 8; r++) {
        int q = t + 256 * r;
        int row = q >> 6;
        int c4 = (q & 63) << 2;
        float4 v = *(const float4*)(emb + (size_t)sidx[row] * KDIM + c4);
        se[row][c4 + 0] = v.x; se[row][c4 + 1] = v.y;
        se[row][c4 + 2] = v.z; se[row][c4 + 3] = v.w;
    }
    __syncthreads();
    const int hw = t & 31;
    const int cg = t >> 5;
    const int b = n0 >> 10;
    const int hwg = (n0 & 1023) + hw;
    const size_t zbase = (size_t)b * (KDIM * 1024) + hwg;
    float acc = 0.0f;
    #pragma unroll
    for (int ci = 0; ci < 32; ci++) {
        int c = cg * 32 + ci;
        float v = se[hw][c];
        size_t off = zbase + (size_t)c * 1024;
        float zv = z[off];
        float d = v - zv;
        acc += d * d;
        out[ZQ_OFF + off] = v;
        out[ZQ1_OFF + off] = v;
    }
    red[t] = acc;
    __syncthreads();
    #pragma unroll
    for (int s = 128; s > 0; s >>= 1) {
        if (t < s) red[t] += red[t + s];
        __syncthreads();
    }
    if (t == 0) g_partials[blockIdx.x] = red[0];
}

// ---------------- kernel B2: parallel histogram ----------------
__global__ void hist_kernel() {
    __shared__ int h[NE];
    const int t = threadIdx.x;       // 32 blocks x 256 threads
    #pragma unroll
    for (int r = 0; r < 4; r++) h[t + 256 * r] = 0;
    __syncthreads();
    const int base = blockIdx.x * 1024;
    #pragma unroll
    for (int r = 0; r < 4; r++) {
        int id = g_idx[base + t + 256 * r];
        atomicAdd(&h[id], 1);
    }
    __syncthreads();
    #pragma unroll
    for (int r = 0; r < 4; r++) {
        int v = h[t + 256 * r];
        if (v) atomicAdd(&g_hist[t + 256 * r], v);
    }
}

// ---------------- kernel B3: loss + perplexity ----------------
__global__ void finalize_kernel(float* __restrict__ out) {
    __shared__ float red[1024];
    const int t = threadIdx.x;       // 1024 threads, 1 block
    red[t] = g_partials[t];
    __syncthreads();
    #pragma unroll
    for (int s = 512; s > 0; s >>= 1) {
        if (t < s) red[t] += red[t + s];
        __syncthreads();
    }
    float loss = red[0] * (1.0f + BETA) / 8388608.0f;
    __syncthreads();
    float p = (float)g_hist[t] / (float)NPIX;
    red[t] = p * logf(p + EPS_P);
    __syncthreads();
    #pragma unroll
    for (int s = 512; s > 0; s >>= 1) {
        if (t < s) red[t] += red[t + s];
        __syncthreads();
    }
    if (t == 0) {
        out[0] = loss;
        out[PERP_OFF] = expf(-red[0]);
    }
}

// ---------------- launch ----------------
extern "C" void kernel_launch(void* const* d_in, const int* in_sizes, int n_in,
                              void* d_out, int out_size) {
    const float* z   = (const float*)d_in[0];
    const float* emb = (const float*)d_in[1];
    float* out = (float*)d_out;

    split_kernel<<<NE, 256>>>(emb);

    cudaFuncSetAttribute(argmin_mma_kernel,
                         cudaFuncAttributeMaxDynamicSharedMemorySize,
                         SMF_TOTAL * 4);
    argmin_mma_kernel<<<NPIX / 128, 256, SMF_TOTAL * 4>>>(z);

    gather_kernel<<<NPIX / 32, 256>>>(z, emb, out);
    hist_kernel<<<32, 256>>>();
    finalize_kernel<<<1, 1024>>>(out);
}

// round 7
// speedup vs baseline: 1.3794x; 1.1526x over previous
#include <cuda_runtime.h>
#include <math.h>
#include <stdint.h>

// ---------------- problem constants ----------------
#define NPIX     32768
#define NE       1024
#define KDIM     256
#define BETA     0.25f
#define EPS_P    1e-10f
#define DELTA    0.2f

// output layout (concatenated, float32)
#define ZQ_OFF    1ull
#define PERP_OFF  8388609ull
#define IDX_OFF   8388610ull
#define ZQ1_OFF   8421378ull

// ---------------- device scratch ----------------
__device__ int   g_idx[NPIX];
__device__ float g_hn_g[NE];
__device__ int   g_hist[NE];
__device__ float g_partials[1024];
__device__ int   g_cnt[NPIX];
__device__ int   g_cand[NPIX * 8];
// emb tf32-hi, k pair-permuted within 8-blocks so (k, k+4) are adjacent
__device__ float g_ehi[NE * KDIM];

// ---------------- smem layout (floats) ----------------
// As   [0, 33280)        : A tf32-hi [128 rows][260] (cols = permuted k)
// Bs   [33280, 47104)    : 3 stages x 4608 = [128 n][36]
// hn   [47104, 48128)
// redv [48128, 48384)    : 128 px x 2 nwarps
// Vs   [48384, 48512)    : per-pixel approx max
#define AS_STRIDE 260
#define SMF_BS    33280
#define BUF_FLOATS 4608
#define SMF_HN    47104
#define SMF_REDV  48128
#define SMF_VS    48384
#define SMF_TOTAL 48512

static __device__ __forceinline__ uint32_t smem_u32(const void* p) {
    uint32_t a;
    asm("{ .reg .u64 t; cvta.to.shared.u64 t, %1; cvt.u32.u64 %0, t; }" : "=r"(a) : "l"(p));
    return a;
}
static __device__ __forceinline__ uint32_t f2tf32(float f) {
    uint32_t u; asm("cvt.rna.tf32.f32 %0, %1;" : "=r"(u) : "f"(f)); return u;
}
static __device__ __forceinline__ void cp16(uint32_t smem, const void* g) {
    asm volatile("cp.async.cg.shared.global [%0], [%1], 16;" :: "r"(smem), "l"(g) : "memory");
}
#define CP_COMMIT() asm volatile("cp.async.commit_group;" ::: "memory")
#define CP_WAIT1()  asm volatile("cp.async.wait_group 1;" ::: "memory")
#define CP_WAIT0()  asm volatile("cp.async.wait_group 0;" ::: "memory")

static __device__ __forceinline__ void mma8(float* c, const uint32_t* a, const uint32_t* b) {
    asm volatile(
        "mma.sync.aligned.m16n8k8.row.col.f32.tf32.tf32.f32 "
        "{%0,%1,%2,%3}, {%4,%5,%6,%7}, {%8,%9}, {%0,%1,%2,%3};"
        : "+f"(c[0]), "+f"(c[1]), "+f"(c[2]), "+f"(c[3])
        : "r"(a[0]), "r"(a[1]), "r"(a[2]), "r"(a[3]), "r"(b[0]), "r"(b[1]));
}

// k permutation within 8-blocks: (k, k+4) become adjacent
static __device__ __forceinline__ int kperm(int k) {
    return (k & ~7) | (((k & 3) << 1) | ((k >> 2) & 1));
}

// ---------------- kernel 0: emb -> tf32 hi (permuted) + half norms + zero hist/cnt ----------------
__global__ void split_kernel(const float* __restrict__ emb) {
    __shared__ float red[256];
    const int c = blockIdx.x;        // 1024 blocks
    const int t = threadIdx.x;       // 256 threads = one k each
    float f = emb[c * KDIM + t];
    uint32_t hu = f2tf32(f);
    g_ehi[c * KDIM + kperm(t)] = __uint_as_float(hu);
    red[t] = f * f;
    int gid = c * 256 + t;
    if (gid < NPIX) g_cnt[gid] = 0;
    __syncthreads();
    #pragma unroll
    for (int s = 128; s > 0; s >>= 1) {
        if (t < s) red[t] += red[t + s];
        __syncthreads();
    }
    if (t == 0) { g_hn_g[c] = 0.5f * red[0]; g_hist[c] = 0; }
}

// ---------------- kernel A: single-pass tf32 mma + candidate collection ----------------
// 256 threads, 8 warps = 4 M-groups x 2 N-groups; warp tile 32(M) x 64(N).
__global__ void __launch_bounds__(256, 1)
argmin_mma_kernel(const float* __restrict__ z) {
    extern __shared__ float sm[];
    float* As   = sm;
    float* hn   = sm + SMF_HN;
    float* redv = sm + SMF_REDV;
    float* Vs   = sm + SMF_VS;
    const uint32_t sb = smem_u32(sm);

    const int tid = threadIdx.x;
    const int wid = tid >> 5;
    const int l   = tid & 31;
    const int qr  = l >> 2;
    const int qc  = l & 3;
    const int mb  = (wid >> 1) * 32;
    const int nb  = (wid & 1) * 64;
    const int m0  = blockIdx.x * 128;

    // ---- B chunk loader (tf32-hi only, 16 KB/chunk) ----
    auto load_chunk = [&](int it, int stage) {
        const int ct = it >> 3, kc = it & 7;
        const float* ghi = g_ehi + (size_t)(ct * 128) * KDIM + kc * 32;
        const uint32_t dhi = sb + (SMF_BS + stage * BUF_FLOATS) * 4;
        #pragma unroll
        for (int r = 0; r < 4; r++) {
            int q = tid + 256 * r;          // 0..1023 16B units
            int n = q >> 3, j = q & 7;
            cp16(dhi + (n * 36 + j * 4) * 4, ghi + (size_t)n * KDIM + j * 4);
        }
        CP_COMMIT();
    };

    load_chunk(0, 0);
    load_chunk(1, 1);

    // ---- prologue: load z tile, convert to tf32-hi, store permuted ----
    {
        const int k = tid;
        const int kp = kperm(k);
        const float* zr = z + (size_t)((m0 >> 10) * 256 + k) * 1024 + (m0 & 1023);
        #pragma unroll
        for (int r = 0; r < 32; r++) {
            float4 v = *(const float4*)(zr + r * 4);
            As[(r * 4 + 0) * AS_STRIDE + kp] = __uint_as_float(f2tf32(v.x));
            As[(r * 4 + 1) * AS_STRIDE + kp] = __uint_as_float(f2tf32(v.y));
            As[(r * 4 + 2) * AS_STRIDE + kp] = __uint_as_float(f2tf32(v.z));
            As[(r * 4 + 3) * AS_STRIDE + kp] = __uint_as_float(f2tf32(v.w));
        }
        #pragma unroll
        for (int r = 0; r < 4; r++) hn[tid + 256 * r] = g_hn_g[tid + 256 * r];
    }
    __syncthreads();

    // per-slot running best + 2 runner-up candidates within DELTA
    float best[4]; int bidx[4];
    float cv[4][2]; int ci[4][2];
    #pragma unroll
    for (int s = 0; s < 4; s++) {
        best[s] = -INFINITY; bidx[s] = 0;
        cv[s][0] = -INFINITY; cv[s][1] = -INFINITY;
        ci[s][0] = 0; ci[s][1] = 0;
    }

    for (int ct = 0; ct < 8; ct++) {
        float acc[2][8][4];
        #pragma unroll
        for (int mf = 0; mf < 2; mf++)
            #pragma unroll
            for (int nf = 0; nf < 8; nf++)
                #pragma unroll
                for (int cc = 0; cc < 4; cc++) acc[mf][nf][cc] = 0.0f;

        for (int kc = 0; kc < 8; kc++) {
            const int it = ct * 8 + kc;
            const int stage = it % 3;
            if (it == 63) { CP_WAIT0(); } else { CP_WAIT1(); }
            __syncthreads();
            if (it + 2 < 64) load_chunk(it + 2, (it + 2) % 3);

            const float* bhB = sm + SMF_BS + stage * BUF_FLOATS;

            #pragma unroll
            for (int ks = 0; ks < 4; ks++) {
                uint32_t af[2][4];
                #pragma unroll
                for (int mf = 0; mf < 2; mf++)
                    #pragma unroll
                    for (int h = 0; h < 2; h++) {
                        int row = mb + qr + mf * 16 + h * 8;
                        float2 f = *(const float2*)(As + row * AS_STRIDE + kc * 32 + ks * 8 + 2 * qc);
                        af[mf][h]     = __float_as_uint(f.x);
                        af[mf][h + 2] = __float_as_uint(f.y);
                    }
                #pragma unroll
                for (int nf = 0; nf < 8; nf++) {
                    const int n = nb + nf * 8 + qr;
                    float2 bh = *(const float2*)(bhB + n * 36 + ks * 8 + 2 * qc);
                    uint32_t bhr[2] = { __float_as_uint(bh.x), __float_as_uint(bh.y) };
                    mma8(acc[0][nf], af[0], bhr);
                    mma8(acc[1][nf], af[1], bhr);
                }
            }
        }

        // epilogue: subtract half-norm, fold into running argmax + candidates
        #pragma unroll
        for (int mf = 0; mf < 2; mf++)
            #pragma unroll
            for (int nf = 0; nf < 8; nf++)
                #pragma unroll
                for (int cc = 0; cc < 4; cc++) {
                    int col = nb + nf * 8 + 2 * qc + (cc & 1);
                    int code = ct * 128 + col;
                    float s = acc[mf][nf][cc] - hn[code];
                    int slot = mf * 2 + (cc >> 1);
                    if (s > best[slot]) {
                        // demote old best into runner-up list
                        float ov = best[slot]; int oi = bidx[slot];
                        if (cv[slot][0] <= cv[slot][1]) {
                            if (ov > cv[slot][0]) { cv[slot][0] = ov; ci[slot][0] = oi; }
                        } else {
                            if (ov > cv[slot][1]) { cv[slot][1] = ov; ci[slot][1] = oi; }
                        }
                        best[slot] = s; bidx[slot] = code;
                    } else if (s > best[slot] - DELTA) {
                        if (cv[slot][0] <= cv[slot][1]) {
                            if (s > cv[slot][0]) { cv[slot][0] = s; ci[slot][0] = code; }
                        } else {
                            if (s > cv[slot][1]) { cv[slot][1] = s; ci[slot][1] = code; }
                        }
                    }
                }
    }

    // per-pixel approx max: reduce over qc lanes, then over the 2 N-warps
    #pragma unroll
    for (int s = 0; s < 4; s++) {
        float v = best[s];
        #pragma unroll
        for (int m = 1; m <= 2; m <<= 1) {
            float ov = __shfl_xor_sync(0xffffffffu, v, m);
            if (ov > v) v = ov;
        }
        if (qc == 0) {
            int row = mb + qr + (s >> 1) * 16 + (s & 1) * 8;
            redv[row * 2 + (wid & 1)] = v;
        }
    }
    __syncthreads();
    if (tid < 128) Vs[tid] = fmaxf(redv[tid * 2], redv[tid * 2 + 1]);
    __syncthreads();

    // emit candidates within DELTA of the pixel's approx max
    #pragma unroll
    for (int s = 0; s < 4; s++) {
        int row = mb + qr + (s >> 1) * 16 + (s & 1) * 8;
        float V = Vs[row];
        int p = m0 + row;
        if (best[s] > V - DELTA) {
            int pos = atomicAdd(&g_cnt[p], 1);
            if (pos < 8) g_cand[p * 8 + pos] = bidx[s];
        }
        if (cv[s][0] > V - DELTA) {
            int pos = atomicAdd(&g_cnt[p], 1);
            if (pos < 8) g_cand[p * 8 + pos] = ci[s][0];
        }
        if (cv[s][1] > V - DELTA) {
            int pos = atomicAdd(&g_cnt[p], 1);
            if (pos < 8) g_cand[p * 8 + pos] = ci[s][1];
        }
    }
}

// ---------------- kernel A2: exact fp32 rescoring of candidates ----------------
// 1 warp per pixel, 8 warps per block
__global__ void __launch_bounds__(256)
rescore_kernel(const float* __restrict__ z, const float* __restrict__ emb) {
    const int w = threadIdx.x >> 5;
    const int l = threadIdx.x & 31;
    const int p = blockIdx.x * 8 + w;
    int cnt = g_cnt[p];
    if (cnt > 8) cnt = 8;
    const int b = p >> 10, hw = p & 1023;
    const float* zp = z + (size_t)b * (KDIM * 1024) + hw;
    float zv[8];
    #pragma unroll
    for (int j = 0; j < 8; j++) zv[j] = zp[(size_t)(j * 32 + l) * 1024];
    float bestv = -INFINITY;
    int besti = 0;
    for (int c = 0; c < cnt; c++) {
        int idx = g_cand[p * 8 + c];
        const float* e = emb + (size_t)idx * KDIM;
        float acc = 0.0f;
        #pragma unroll
        for (int j = 0; j < 8; j++) acc = fmaf(zv[j], e[j * 32 + l], acc);
        #pragma unroll
        for (int m = 16; m >= 1; m >>= 1) acc += __shfl_xor_sync(0xffffffffu, acc, m);
        float s = acc - g_hn_g[idx];
        if (s > bestv || (s == bestv && idx < besti)) { bestv = s; besti = idx; }
    }
    if (l == 0) g_idx[p] = besti;
}

// ---------------- kernel B1: gather z_q/z_q1 + squared-error partials + idx out ----------------
__global__ void __launch_bounds__(256)
gather_kernel(const float* __restrict__ z, const float* __restrict__ emb,
              float* __restrict__ out) {
    __shared__ float se[32][257];
    __shared__ int sidx[32];
    __shared__ float red[256];
    const int t = threadIdx.x;
    const int n0 = blockIdx.x * 32;
    if (t < 32) sidx[t] = g_idx[n0 + t];
    __syncthreads();
    if (t < 32) out[IDX_OFF + n0 + t] = (float)sidx[t];
    #pragma unroll
    for (int r = 0; r < 8; r++) {
        int q = t + 256 * r;
        int row = q >> 6;
        int c4 = (q & 63) << 2;
        float4 v = *(const float4*)(emb + (size_t)sidx[row] * KDIM + c4);
        se[row][c4 + 0] = v.x; se[row][c4 + 1] = v.y;
        se[row][c4 + 2] = v.z; se[row][c4 + 3] = v.w;
    }
    __syncthreads();
    const int hw = t & 31;
    const int cg = t >> 5;
    const int b = n0 >> 10;
    const int hwg = (n0 & 1023) + hw;
    const size_t zbase = (size_t)b * (KDIM * 1024) + hwg;
    float acc = 0.0f;
    #pragma unroll
    for (int ci = 0; ci < 32; ci++) {
        int c = cg * 32 + ci;
        float v = se[hw][c];
        size_t off = zbase + (size_t)c * 1024;
        float zv = z[off];
        float d = v - zv;
        acc += d * d;
        out[ZQ_OFF + off] = v;
        out[ZQ1_OFF + off] = v;
    }
    red[t] = acc;
    __syncthreads();
    #pragma unroll
    for (int s = 128; s > 0; s >>= 1) {
        if (t < s) red[t] += red[t + s];
        __syncthreads();
    }
    if (t == 0) g_partials[blockIdx.x] = red[0];
}

// ---------------- kernel B2: parallel histogram ----------------
__global__ void hist_kernel() {
    __shared__ int h[NE];
    const int t = threadIdx.x;       // 32 blocks x 256 threads
    #pragma unroll
    for (int r = 0; r < 4; r++) h[t + 256 * r] = 0;
    __syncthreads();
    const int base = blockIdx.x * 1024;
    #pragma unroll
    for (int r = 0; r < 4; r++) {
        int id = g_idx[base + t + 256 * r];
        atomicAdd(&h[id], 1);
    }
    __syncthreads();
    #pragma unroll
    for (int r = 0; r < 4; r++) {
        int v = h[t + 256 * r];
        if (v) atomicAdd(&g_hist[t + 256 * r], v);
    }
}

// ---------------- kernel B3: loss + perplexity ----------------
__global__ void finalize_kernel(float* __restrict__ out) {
    __shared__ float red[1024];
    const int t = threadIdx.x;       // 1024 threads, 1 block
    red[t] = g_partials[t];
    __syncthreads();
    #pragma unroll
    for (int s = 512; s > 0; s >>= 1) {
        if (t < s) red[t] += red[t + s];
        __syncthreads();
    }
    float loss = red[0] * (1.0f + BETA) / 8388608.0f;
    __syncthreads();
    float p = (float)g_hist[t] / (float)NPIX;
    red[t] = p * logf(p + EPS_P);
    __syncthreads();
    #pragma unroll
    for (int s = 512; s > 0; s >>= 1) {
        if (t < s) red[t] += red[t + s];
        __syncthreads();
    }
    if (t == 0) {
        out[0] = loss;
        out[PERP_OFF] = expf(-red[0]);
    }
}

// ---------------- launch ----------------
extern "C" void kernel_launch(void* const* d_in, const int* in_sizes, int n_in,
                              void* d_out, int out_size) {
    const float* z   = (const float*)d_in[0];
    const float* emb = (const float*)d_in[1];
    float* out = (float*)d_out;

    split_kernel<<<NE, 256>>>(emb);

    cudaFuncSetAttribute(argmin_mma_kernel,
                         cudaFuncAttributeMaxDynamicSharedMemorySize,
                         SMF_TOTAL * 4);
    argmin_mma_kernel<<<NPIX / 128, 256, SMF_TOTAL * 4>>>(z);

    rescore_kernel<<<NPIX / 8, 256>>>(z, emb);
    gather_kernel<<<NPIX / 32, 256>>>(z, emb, out);
    hist_kernel<<<32, 256>>>();
    finalize_kernel<<<1, 1024>>>(out);
}